// round 16
// baseline (speedup 1.0000x reference)
#include <cuda_runtime.h>
#include <cuda_bf16.h>
#include <math.h>
#include <stdint.h>

#define BB 32
#define NN 196
#define TT 128
#define DH 512
#define VV 10000
#define VPAD 10112
#define GRID_P 128

typedef __nv_bfloat16 bf16;

// decode_loop dynamic smem: weight banks + activation tile, [32 rows][520 bf16] each
#define ROWS32 32
#define KSTR 520
#define BANKE (ROWS32 * KSTR)
#define OFF_WWH 0
#define OFF_WWL (1 * BANKE)
#define OFF_WCH (2 * BANKE)
#define OFF_WCL (3 * BANKE)
#define OFF_AH  (4 * BANKE)
#define OFF_AL  (5 * BANKE)
#define DEC_SMEM (6 * BANKE * 2)       // 199,680 bytes

// flag layout (words; 64-word line stride)
#define FS_INIT 0
#define FS_HWH  64
#define FS_CTX  128
#define FS_GX   192
#define FS_GH   256
#define FS_H    320
#define FS_MINI 1024                   // + b*64
#define FS_TOTAL (1024 + BB * 64)

// ---------------- device scratch (static, no allocation) ----------------
__device__ float g_keys[BB * NN * DH];
__device__ float g_wk  [BB * NN * DH];
__device__ float g_Gx  [BB * TT * 4 * DH];
__device__ float g_c   [BB * DH];
__device__ float g_hwh [BB * DH];
__device__ float g_gh  [BB * 4 * DH];
__device__ float g_gx  [BB * 4 * DH];
__device__ float g_ctxp[4][BB * DH];
__device__ float g_cm[BB * 4], g_cs[BB * 4];
__device__ unsigned g_sync[FS_TOTAL];
__device__ bf16 g_hall_hi[BB * TT * DH], g_hall_lo[BB * TT * DH];
__device__ bf16 g_w_hi[VPAD * DH], g_w_lo[VPAD * DH];   // rows >= VV stay zero
__device__ bf16 g_x_hi[BB * TT * DH], g_x_lo[BB * TT * DH];
__device__ bf16 g_p_hi[BB * NN * 768], g_p_lo[BB * NN * 768];
__device__ bf16 g_kvw_hi[512 * 768], g_kvw_lo[512 * 768];
__device__ bf16 g_awk_hi[512 * 512], g_awk_lo[512 * 512];
__device__ bf16 g_wih_hi[2048 * 512], g_wih_lo[2048 * 512];     // Wih x-half
__device__ bf16 g_keys_hi[BB * NN * DH], g_keys_lo[BB * NN * DH];
__device__ bf16 g_whh_hi[2048 * 512], g_whh_lo[2048 * 512];     // W_hh
__device__ bf16 g_wh_hi[512 * 512],  g_wh_lo[512 * 512];        // attn_Wh
__device__ bf16 g_wihc_hi[2048 * 512], g_wihc_lo[2048 * 512];   // Wih ctx-half
__device__ bf16 g_hb_hi[BB * DH], g_hb_lo[BB * DH];             // current h
__device__ bf16 g_ctxb_hi[BB * DH], g_ctxb_lo[BB * DH];         // current ctx

__device__ __forceinline__ float fast_tanh(float x) {
    float y; asm("tanh.approx.f32 %0, %1;" : "=f"(y) : "f"(x)); return y;
}
__device__ __forceinline__ float sigm(float x) { return 1.f / (1.f + expf(-x)); }
__device__ __forceinline__ void split_bf16(float v, bf16* hi, bf16* lo) {
    const bf16 h = __float2bfloat16(v);
    *hi = h;
    *lo = __float2bfloat16(v - __bfloat162float(h));
}

// release-arrive / acquire-poll primitives
__device__ __forceinline__ void red_release_add(unsigned* p) {
    asm volatile("red.release.gpu.global.add.u32 [%0], %1;" :: "l"(p), "r"(1u) : "memory");
}
__device__ __forceinline__ unsigned ld_acquire(const unsigned* p) {
    unsigned v;
    asm volatile("ld.acquire.gpu.global.u32 %0, [%1];" : "=r"(v) : "l"(p) : "memory");
    return v;
}
__device__ __forceinline__ void wait_flag(unsigned* p, unsigned target) {
    while (ld_acquire(p) < target) { __nanosleep(20); }
}

// ---------------- mma.sync helpers ----------------
__device__ __forceinline__ uint32_t smem_u32(const void* p) {
    uint32_t a;
    asm("{ .reg .u64 t; cvta.to.shared.u64 t, %1; cvt.u32.u64 %0, t; }" : "=r"(a) : "l"(p));
    return a;
}
__device__ __forceinline__ void ldsm4(uint32_t* r, uint32_t addr) {
    asm volatile("ldmatrix.sync.aligned.m8n8.x4.shared.b16 {%0,%1,%2,%3}, [%4];"
        : "=r"(r[0]), "=r"(r[1]), "=r"(r[2]), "=r"(r[3]) : "r"(addr));
}
__device__ __forceinline__ void ldsm2(uint32_t* r, uint32_t addr) {
    asm volatile("ldmatrix.sync.aligned.m8n8.x2.shared.b16 {%0,%1}, [%2];"
        : "=r"(r[0]), "=r"(r[1]) : "r"(addr));
}
__device__ __forceinline__ void mma16816(float* c, const uint32_t* a, const uint32_t* b) {
    asm volatile("mma.sync.aligned.m16n8k16.row.col.f32.bf16.bf16.f32 "
        "{%0,%1,%2,%3}, {%4,%5,%6,%7}, {%8,%9}, {%0,%1,%2,%3};"
        : "+f"(c[0]), "+f"(c[1]), "+f"(c[2]), "+f"(c[3])
        : "r"(a[0]), "r"(a[1]), "r"(a[2]), "r"(a[3]), "r"(b[0]), "r"(b[1]));
}
__device__ __forceinline__ void cp16(uint32_t smem_addr, const void* gptr) {
    asm volatile("cp.async.cg.shared.global [%0], [%1], 16;"
        :: "r"(smem_addr), "l"(gptr));
}
#define CP_COMMIT() asm volatile("cp.async.commit_group;" ::: "memory")
#define CP_WAIT(n)  asm volatile("cp.async.wait_group %0;" :: "n"(n) : "memory")

// ---------------- generic split-bf16 MMA GEMM (validated) ----------------
#define LSTR 40
#define MAT_B (128 * LSTR * 2)
#define BUF_B (4 * MAT_B)
#define MMA_SMEM (2 * BUF_B)
__global__ __launch_bounds__(256, 2) void mma_nt(
    const bf16* __restrict__ Ah, const bf16* __restrict__ Al,
    const bf16* __restrict__ Bh, const bf16* __restrict__ Bl,
    const float* __restrict__ bias1, const float* __restrict__ bias2,
    float* __restrict__ C, int ldc, int nLimit, int kChunks, int ldA, int ldB,
    bf16* __restrict__ Chi, bf16* __restrict__ Clo)
{
    extern __shared__ char lsm[];
    const uint32_t u0 = smem_u32(lsm);

    const int tid = threadIdx.x;
    const int wid = tid >> 5, lane = tid & 31;
    const int nBase = blockIdx.x * 128;
    const int mBase = blockIdx.y * 128;
    const int wm = (wid & 3) * 32;
    const int wn = (wid >> 2) * 64;

    float acc[2][8][4];
#pragma unroll
    for (int i = 0; i < 2; i++)
#pragma unroll
        for (int j = 0; j < 8; j++)
#pragma unroll
            for (int k = 0; k < 4; k++) acc[i][j][k] = 0.f;

    const int cr = tid >> 1;
    const int cs = (tid & 1) * 2;

    const bf16* gsrc[4] = {
        Ah + (size_t)(mBase + cr) * ldA, Al + (size_t)(mBase + cr) * ldA,
        Bh + (size_t)(nBase + cr) * ldB, Bl + (size_t)(nBase + cr) * ldB };
    const uint32_t sdst = u0 + (cr * LSTR + cs * 8) * 2;

    auto stage = [&](int ch, int buf) {
        const int goff = ch * 32 + cs * 8;
#pragma unroll
        for (int m = 0; m < 4; m++) {
            const uint32_t d = sdst + buf * BUF_B + m * MAT_B;
            cp16(d, gsrc[m] + goff);
            cp16(d + 16, gsrc[m] + goff + 8);
        }
        CP_COMMIT();
    };

    stage(0, 0);

    for (int ch = 0; ch < kChunks; ch++) {
        const int cur = ch & 1;
        if (ch + 1 < kChunks) { stage(ch + 1, cur ^ 1); CP_WAIT(1); }
        else                  { CP_WAIT(0); }
        __syncthreads();

        const uint32_t uAh = u0 + cur * BUF_B;
        const uint32_t uAl = uAh + MAT_B;
        const uint32_t uBh = uAl + MAT_B;
        const uint32_t uBl = uBh + MAT_B;

#pragma unroll
        for (int ks = 0; ks < 2; ks++) {
            uint32_t ah[2][4], al[2][4], bh[8][2], bl[8][2];
#pragma unroll
            for (int mt = 0; mt < 2; mt++) {
                const uint32_t off =
                    ((wm + mt * 16 + (lane & 15)) * LSTR + ks * 16 + (lane >> 4) * 8) * 2;
                ldsm4(ah[mt], uAh + off);
                ldsm4(al[mt], uAl + off);
            }
#pragma unroll
            for (int p = 0; p < 4; p++) {
                const uint32_t off =
                    ((wn + p * 16 + ((lane >> 4) & 1) * 8 + (lane & 7)) * LSTR +
                     ks * 16 + ((lane >> 3) & 1) * 8) * 2;
                uint32_t r4[4];
                ldsm4(r4, uBh + off);
                bh[2 * p][0] = r4[0]; bh[2 * p][1] = r4[1];
                bh[2 * p + 1][0] = r4[2]; bh[2 * p + 1][1] = r4[3];
                ldsm4(r4, uBl + off);
                bl[2 * p][0] = r4[0]; bl[2 * p][1] = r4[1];
                bl[2 * p + 1][0] = r4[2]; bl[2 * p + 1][1] = r4[3];
            }
#pragma unroll
            for (int mt = 0; mt < 2; mt++)
#pragma unroll
                for (int nt = 0; nt < 8; nt++) {
                    mma16816(acc[mt][nt], ah[mt], bh[nt]);
                    mma16816(acc[mt][nt], ah[mt], bl[nt]);
                    mma16816(acc[mt][nt], al[mt], bh[nt]);
                }
        }
        __syncthreads();
    }

    const int erow = lane >> 2;
    const int ecol = (lane & 3) * 2;
#pragma unroll
    for (int mt = 0; mt < 2; mt++) {
#pragma unroll
        for (int nt = 0; nt < 8; nt++) {
            const int gn = nBase + wn + nt * 8 + ecol;
            if (gn >= nLimit) continue;
            float b0 = 0.f, b1 = 0.f;
            if (bias1) { b0 += bias1[gn]; b1 += bias1[gn + 1]; }
            if (bias2) { b0 += bias2[gn]; b1 += bias2[gn + 1]; }
            const int r0 = mBase + wm + mt * 16 + erow;
            const float v00 = acc[mt][nt][0] + b0, v01 = acc[mt][nt][1] + b1;
            const float v10 = acc[mt][nt][2] + b0, v11 = acc[mt][nt][3] + b1;
            if (C) {
                *(float2*)&C[(size_t)r0 * ldc + gn] = make_float2(v00, v01);
                *(float2*)&C[(size_t)(r0 + 8) * ldc + gn] = make_float2(v10, v11);
            }
            if (Chi) {
                const size_t i0 = (size_t)r0 * ldc + gn;
                const size_t i1 = (size_t)(r0 + 8) * ldc + gn;
                split_bf16(v00, &Chi[i0], &Clo[i0]);
                split_bf16(v01, &Chi[i0 + 1], &Clo[i0 + 1]);
                split_bf16(v10, &Chi[i1], &Clo[i1]);
                split_bf16(v11, &Chi[i1 + 1], &Clo[i1 + 1]);
            }
        }
    }
}

// ---------------- all input conversions + embedding gather ----------------
#define NB_GATH 8192
#define NB_OUTW 20000
#define NB_PTCH 18816
#define NB_KVW  1536
#define NB_AWK  1024
#define NB_WIHX 4096
#define NB_WHH  4096
#define NB_WH   1024
#define NB_WIHC 4096
__global__ void gather_conv(const int* __restrict__ ids, const float* __restrict__ emb,
                            const float* __restrict__ outW, const float* __restrict__ patches,
                            const float* __restrict__ kvW, const float* __restrict__ aWk,
                            const float* __restrict__ Wih, const float* __restrict__ Whh,
                            const float* __restrict__ aWh)
{
    int blk = blockIdx.x;
    const int tid = threadIdx.x;
    if (blk < NB_GATH) {
        const int i = blk * 256 + tid;
        const int d = i & (DH - 1);
        const int bt = i >> 9;
        split_bf16(emb[(size_t)ids[bt] * DH + d], &g_x_hi[i], &g_x_lo[i]);
        return;
    }
    blk -= NB_GATH;
    if (blk < NB_OUTW) {
        const int j = blk * 256 + tid;
        if (j < VV * DH) split_bf16(outW[j], &g_w_hi[j], &g_w_lo[j]);
        return;
    }
    blk -= NB_OUTW;
    if (blk < NB_PTCH) {
        const int j = blk * 256 + tid;
        split_bf16(patches[j], &g_p_hi[j], &g_p_lo[j]);
        return;
    }
    blk -= NB_PTCH;
    if (blk < NB_KVW) {
        const int j = blk * 256 + tid;
        split_bf16(kvW[j], &g_kvw_hi[j], &g_kvw_lo[j]);
        return;
    }
    blk -= NB_KVW;
    if (blk < NB_AWK) {
        const int j = blk * 256 + tid;
        split_bf16(aWk[j], &g_awk_hi[j], &g_awk_lo[j]);
        return;
    }
    blk -= NB_AWK;
    if (blk < NB_WIHX) {
        const int j = blk * 256 + tid;
        const int r = j >> 9, c = j & 511;
        split_bf16(Wih[(size_t)r * 1024 + c], &g_wih_hi[j], &g_wih_lo[j]);
        return;
    }
    blk -= NB_WIHX;
    if (blk < NB_WHH) {
        const int j = blk * 256 + tid;
        split_bf16(Whh[j], &g_whh_hi[j], &g_whh_lo[j]);
        return;
    }
    blk -= NB_WHH;
    if (blk < NB_WH) {
        const int j = blk * 256 + tid;
        split_bf16(aWh[j], &g_wh_hi[j], &g_wh_lo[j]);
        return;
    }
    blk -= NB_WH;
    {
        const int j = blk * 256 + tid;
        const int r = j >> 9, c = j & 511;
        split_bf16(Wih[(size_t)r * 1024 + 512 + c], &g_wihc_hi[j], &g_wihc_lo[j]);
    }
}

// ---------------- persistent decode loop: dataflow pipeline, producer flags ----------------
__global__ __launch_bounds__(256, 1) void decode_loop(
    const float* __restrict__ av,
    const float* __restrict__ lnw, const float* __restrict__ lnb,
    const float* __restrict__ cls,
    const float* __restrict__ ihW, const float* __restrict__ ihb,
    const float* __restrict__ icW, const float* __restrict__ icb)
{
    extern __shared__ bf16 dsm[];
    __shared__ float s_v[512];
    __shared__ float s_hwh[512];
    __shared__ float s_sc[49];
    __shared__ float s_e[64];
    __shared__ float s_r0[8], s_r1[8], s_mv[2];

    const int tid = threadIdx.x;
    const int bid = blockIdx.x;
    const int warp = tid >> 5, lane = tid & 31;
    const int gwarp = bid * 8 + warp;
    const uint32_t u0 = smem_u32(dsm);

    // ---- one-time weight staging ----
    if (bid < 16) {                 // bankW <- attn_Wh rows [bid*32, +32)
        for (int idx = tid; idx < ROWS32 * 64; idx += 256) {
            const int row = idx >> 6, seg = idx & 63;
            const int gr = bid * 32 + row;
            *(uint4*)(dsm + OFF_WWH + row * KSTR + seg * 8) = *(const uint4*)(g_wh_hi + (size_t)gr * 512 + seg * 8);
            *(uint4*)(dsm + OFF_WWL + row * KSTR + seg * 8) = *(const uint4*)(g_wh_lo + (size_t)gr * 512 + seg * 8);
        }
    } else if (bid >= 64) {         // bankW <- Whh rows [(bid-64)*32, +32)
        for (int idx = tid; idx < ROWS32 * 64; idx += 256) {
            const int row = idx >> 6, seg = idx & 63;
            const int gr = (bid - 64) * 32 + row;
            *(uint4*)(dsm + OFF_WWH + row * KSTR + seg * 8) = *(const uint4*)(g_whh_hi + (size_t)gr * 512 + seg * 8);
            *(uint4*)(dsm + OFF_WWL + row * KSTR + seg * 8) = *(const uint4*)(g_whh_lo + (size_t)gr * 512 + seg * 8);
        }
    }
    if (bid < 64) {                 // bankC <- Wih-ctx rows [bid*32, +32)
        for (int idx = tid; idx < ROWS32 * 64; idx += 256) {
            const int row = idx >> 6, seg = idx & 63;
            const int gr = bid * 32 + row;
            *(uint4*)(dsm + OFF_WCH + row * KSTR + seg * 8) = *(const uint4*)(g_wihc_hi + (size_t)gr * 512 + seg * 8);
            *(uint4*)(dsm + OFF_WCL + row * KSTR + seg * 8) = *(const uint4*)(g_wihc_lo + (size_t)gr * 512 + seg * 8);
        }
    }
    for (int k = tid; k < 512; k += 256) s_v[k] = av[k];

    // A-tile loader (32 x 512 hi/lo)
    auto load_A = [&](const bf16* hi, const bf16* lo) {
        for (int idx = tid; idx < 2048; idx += 256) {
            const int row = idx >> 6, seg = idx & 63;
            *(uint4*)(dsm + OFF_AH + row * KSTR + seg * 8) = *(const uint4*)(hi + row * 512 + seg * 8);
            *(uint4*)(dsm + OFF_AL + row * KSTR + seg * 8) = *(const uint4*)(lo + row * 512 + seg * 8);
        }
    };

    auto gate_mma = [&](uint32_t uBh, uint32_t uBl, float* acc) {
        const int mt = warp & 1, nt = warp >> 1;
        const uint32_t uAh = u0 + OFF_AH * 2, uAl = u0 + OFF_AL * 2;
        const uint32_t a_off = ((mt * 16 + (lane & 15)) * KSTR + (lane >> 4) * 8) * 2;
        const uint32_t b_off = ((nt * 8 + (lane & 7)) * KSTR + ((lane >> 3) & 1) * 8) * 2;
#pragma unroll 4
        for (int ks = 0; ks < 32; ks++) {
            const uint32_t kb = ks * 32;
            uint32_t ah[4], al[4], bh[2], bl[2];
            ldsm4(ah, uAh + a_off + kb);
            ldsm4(al, uAl + a_off + kb);
            ldsm2(bh, uBh + b_off + kb);
            ldsm2(bl, uBl + b_off + kb);
            mma16816(acc, ah, bh);
            mma16816(acc, ah, bl);
            mma16816(acc, al, bh);
        }
    };

    // ---- h0/c0 (folded) ----
    for (int j = gwarp; j < 2 * BB * DH; j += GRID_P * 8) {
        const int sel = (j >= BB * DH);
        const int r = sel ? j - BB * DH : j;
        const int b = r >> 9, d = r & (DH - 1);
        const float4* W4 = (const float4*)((sel ? icW : ihW) + (size_t)d * 768);
        const float4* x4 = (const float4*)(cls + (size_t)b * 768);
        float acc = 0.f;
#pragma unroll
        for (int p = 0; p < 6; p++) {
            float4 w = W4[lane + 32 * p];
            float4 x = x4[lane + 32 * p];
            acc += w.x * x.x + w.y * x.y + w.z * x.z + w.w * x.w;
        }
#pragma unroll
        for (int o = 16; o; o >>= 1) acc += __shfl_xor_sync(0xffffffffu, acc, o);
        if (lane == 0) {
            if (sel) g_c[b * DH + d] = acc + icb[d];
            else     split_bf16(acc + ihb[d], &g_hb_hi[b * DH + d], &g_hb_lo[b * DH + d]);
        }
    }
    // one-time full barrier
    __syncthreads();
    if (tid == 0) {
        red_release_add(&g_sync[FS_INIT]);
        wait_flag(&g_sync[FS_INIT], (unsigned)GRID_P);
    }
    __syncthreads();

    for (int t = 0; t < TT; t++) {
        // ======== hwh phase (16 CTAs) ========
        if (bid < 16) {
            if (tid == 0 && t > 0) wait_flag(&g_sync[FS_H], 32u * (unsigned)t);
            __syncthreads();
            load_A(g_hb_hi, g_hb_lo);
            __syncthreads();
            float acc[4] = {0.f, 0.f, 0.f, 0.f};
            gate_mma(u0 + OFF_WWH * 2, u0 + OFF_WWL * 2, acc);
            const int mt = warp & 1, nt = warp >> 1;
            const int b0 = mt * 16 + (lane >> 2);
            const int r = bid * 32 + nt * 8 + (lane & 3) * 2;
            g_hwh[b0 * 512 + r] = acc[0];       g_hwh[b0 * 512 + r + 1] = acc[1];
            g_hwh[(b0 + 8) * 512 + r] = acc[2]; g_hwh[(b0 + 8) * 512 + r + 1] = acc[3];
            __syncthreads();
            if (tid == 0) red_release_add(&g_sync[FS_HWH]);
        }

        // ======== B phase (all 128 CTAs) ========
        if (tid == 0) wait_flag(&g_sync[FS_HWH], 16u * (unsigned)(t + 1));
        __syncthreads();
        {
            const int b = bid >> 2, p = bid & 3;
            for (int k = tid; k < 512; k += 256) s_hwh[k] = g_hwh[b * 512 + k];
            __syncthreads();

            for (int n = warp; n < 49; n += 8) {
                const int ng = p * 49 + n;
                const float4* wk4 = (const float4*)(g_wk + ((size_t)(b * NN + ng)) * 512);
                const float4* hw4 = (const float4*)s_hwh;
                const float4* v4  = (const float4*)s_v;
                float s = 0.f;
#pragma unroll
                for (int i = 0; i < 4; i++) {
                    const float4 a = wk4[lane + 32 * i];
                    const float4 c = hw4[lane + 32 * i];
                    const float4 w = v4[lane + 32 * i];
                    s += fast_tanh(a.x + c.x) * w.x + fast_tanh(a.y + c.y) * w.y +
                         fast_tanh(a.z + c.z) * w.z + fast_tanh(a.w + c.w) * w.w;
                }
#pragma unroll
                for (int o = 16; o; o >>= 1) s += __shfl_xor_sync(0xffffffffu, s, o);
                if (lane == 0) s_sc[n] = s;
            }
            __syncthreads();

            if (warp == 0) {
                const float x0 = (lane < 49) ? s_sc[lane] : -1e30f;
                const float x1 = (lane + 32 < 49) ? s_sc[lane + 32] : -1e30f;
                float m = fmaxf(x0, x1);
#pragma unroll
                for (int o = 16; o; o >>= 1) m = fmaxf(m, __shfl_xor_sync(0xffffffffu, m, o));
                const float e0 = (lane < 49) ? __expf(x0 - m) : 0.f;
                const float e1 = (lane + 32 < 49) ? __expf(x1 - m) : 0.f;
                if (lane < 49) s_e[lane] = e0;
                if (lane + 32 < 49) s_e[lane + 32] = e1;
                float su = e0 + e1;
#pragma unroll
                for (int o = 16; o; o >>= 1) su += __shfl_xor_sync(0xffffffffu, su, o);
                if (lane == 0) { g_cm[b * 4 + p] = m; g_cs[b * 4 + p] = su; }
            }
            __syncthreads();

#pragma unroll
            for (int u = 0; u < 2; u++) {
                const int d = tid + 256 * u;
                const float* Kp = g_keys + ((size_t)(b * NN + p * 49)) * 512 + d;
                float a = 0.f;
#pragma unroll 7
                for (int i = 0; i < 49; i++) a = fmaf(s_e[i], Kp[(size_t)i * 512], a);
                g_ctxp[p][b * 512 + d] = a;
            }

            __syncthreads();
            if (tid == 0) {
                red_release_add(&g_sync[FS_MINI + b * 64]);
                wait_flag(&g_sync[FS_MINI + b * 64], 4u * (unsigned)(t + 1));
            }
            __syncthreads();

            if (tid < 128) {
                const int d = p * 128 + tid;
                const float m0 = g_cm[b*4+0], m1 = g_cm[b*4+1], m2 = g_cm[b*4+2], m3 = g_cm[b*4+3];
                const float m = fmaxf(fmaxf(m0, m1), fmaxf(m2, m3));
                const float e0 = __expf(m0 - m), e1 = __expf(m1 - m);
                const float e2 = __expf(m2 - m), e3 = __expf(m3 - m);
                const float den = e0 * g_cs[b*4+0] + e1 * g_cs[b*4+1] +
                                  e2 * g_cs[b*4+2] + e3 * g_cs[b*4+3];
                const float v = (e0 * g_ctxp[0][b*512+d] + e1 * g_ctxp[1][b*512+d] +
                                 e2 * g_ctxp[2][b*512+d] + e3 * g_ctxp[3][b*512+d]) / den;
                split_bf16(v, &g_ctxb_hi[b * 512 + d], &g_ctxb_lo[b * 512 + d]);
            }
        }
        __syncthreads();
        if (tid == 0) red_release_add(&g_sync[FS_CTX]);

        // ======== gx (CTAs 0-63) ‖ gh (CTAs 64-127) ========
        if (bid < 64) {
            if (tid == 0) wait_flag(&g_sync[FS_CTX], 128u * (unsigned)(t + 1));
            __syncthreads();
            load_A(g_ctxb_hi, g_ctxb_lo);
            __syncthreads();
            float acc[4] = {0.f, 0.f, 0.f, 0.f};
            gate_mma(u0 + OFF_WCH * 2, u0 + OFF_WCL * 2, acc);
            const int mt = warp & 1, nt = warp >> 1;
            const int b0 = mt * 16 + (lane >> 2);
            const int r = bid * 32 + nt * 8 + (lane & 3) * 2;
            g_gx[b0 * 2048 + r] = acc[0];       g_gx[b0 * 2048 + r + 1] = acc[1];
            g_gx[(b0 + 8) * 2048 + r] = acc[2]; g_gx[(b0 + 8) * 2048 + r + 1] = acc[3];
            __syncthreads();
            if (tid == 0) red_release_add(&g_sync[FS_GX]);
        } else {
            // gh: h(t) is stable until D(t); no wait needed (B already passed)
            load_A(g_hb_hi, g_hb_lo);
            __syncthreads();
            float acc[4] = {0.f, 0.f, 0.f, 0.f};
            gate_mma(u0 + OFF_WWH * 2, u0 + OFF_WWL * 2, acc);
            const int mt = warp & 1, nt = warp >> 1;
            const int b0 = mt * 16 + (lane >> 2);
            const int r = (bid - 64) * 32 + nt * 8 + (lane & 3) * 2;
            g_gh[b0 * 2048 + r] = acc[0];       g_gh[b0 * 2048 + r + 1] = acc[1];
            g_gh[(b0 + 8) * 2048 + r] = acc[2]; g_gh[(b0 + 8) * 2048 + r + 1] = acc[3];
            __syncthreads();
            if (tid == 0) red_release_add(&g_sync[FS_GH]);
        }

        // ======== D phase (32 CTAs): cell + LayerNorm ========
        if (bid < 32) {
            if (tid == 0) {
                wait_flag(&g_sync[FS_GX], 64u * (unsigned)(t + 1));
                wait_flag(&g_sync[FS_GH], 64u * (unsigned)(t + 1));
            }
            __syncthreads();
            const int b = bid;
            const float* Gx = g_Gx + ((size_t)(b * TT + t)) * 2048;
            const float* Gh = g_gh + (size_t)b * 2048;
            const float* Gc = g_gx + (size_t)b * 2048;
            float hr[2];
            float sum = 0.f, ssq = 0.f;
#pragma unroll
            for (int u = 0; u < 2; u++) {
                const int d = tid + 256 * u;
                const float gi = Gx[d]        + Gh[d]        + Gc[d];
                const float gf = Gx[512 + d]  + Gh[512 + d]  + Gc[512 + d];
                const float gg = Gx[1024 + d] + Gh[1024 + d] + Gc[1024 + d];
                const float go = Gx[1536 + d] + Gh[1536 + d] + Gc[1536 + d];
                const float c_old = g_c[b * DH + d];
                const float cn = sigm(gf) * c_old + sigm(gi) * tanhf(gg);
                g_c[b * DH + d] = cn;
                const float h = sigm(go) * tanhf(cn);
                hr[u] = h; sum += h; ssq += h * h;
            }
#pragma unroll
            for (int o = 16; o; o >>= 1) {
                sum += __shfl_xor_sync(0xffffffffu, sum, o);
                ssq += __shfl_xor_sync(0xffffffffu, ssq, o);
            }
            if (lane == 0) { s_r0[warp] = sum; s_r1[warp] = ssq; }
            __syncthreads();
            if (tid < 8) {
                float s = s_r0[tid], qq = s_r1[tid];
#pragma unroll
                for (int o = 4; o; o >>= 1) {
                    s += __shfl_xor_sync(0x000000ffu, s, o);
                    qq += __shfl_xor_sync(0x000000ffu, qq, o);
                }
                if (tid == 0) { s_mv[0] = s * (1.f / DH); s_mv[1] = qq * (1.f / DH); }
            }
            __syncthreads();
            const float mu = s_mv[0];
            const float var = s_mv[1] - mu * mu;
            const float rstd = rsqrtf(var + 1e-5f);
#pragma unroll
            for (int u = 0; u < 2; u++) {
                const int d = tid + 256 * u;
                const float h = (hr[u] - mu) * rstd * lnw[d] + lnb[d];
                const bf16 hi = __float2bfloat16(h);
                const bf16 lo = __float2bfloat16(h - __bfloat162float(hi));
                const size_t idx = ((size_t)(b * TT + t)) * DH + d;
                g_hall_hi[idx] = hi; g_hall_lo[idx] = lo;
                g_hb_hi[b * DH + d] = hi; g_hb_lo[b * DH + d] = lo;
            }
            __syncthreads();
            if (tid == 0) red_release_add(&g_sync[FS_H]);
        }
    }
}

// ---------------- launch ----------------
extern "C" void kernel_launch(void* const* d_in, const int* in_sizes, int n_in,
                              void* d_out, int out_size)
{
    const float* patches = (const float*)d_in[0];
    const float* cls     = (const float*)d_in[1];
    const int*   tgt     = (const int*)  d_in[2];
    const float* emb     = (const float*)d_in[3];
    const float* kvW     = (const float*)d_in[4];
    const float* kvb     = (const float*)d_in[5];
    const float* ihW     = (const float*)d_in[6];
    const float* ihb     = (const float*)d_in[7];
    const float* icW     = (const float*)d_in[8];
    const float* icb     = (const float*)d_in[9];
    const float* aWh     = (const float*)d_in[10];
    const float* aWk     = (const float*)d_in[11];
    const float* av      = (const float*)d_in[12];
    const float* Wih     = (const float*)d_in[13];
    const float* Whh     = (const float*)d_in[14];
    const float* bih     = (const float*)d_in[15];
    const float* bhh     = (const float*)d_in[16];
    const float* lnw     = (const float*)d_in[17];
    const float* lnb     = (const float*)d_in[18];
    const float* outW    = (const float*)d_in[19];
    const float* outb    = (const float*)d_in[20];
    float* out = (float*)d_out;

    float *keys, *wk, *Gx;
    bf16 *xh, *xl, *ph, *pl, *kvh, *kvl, *awh, *awl, *wihx_h, *wihx_l;
    bf16 *kh, *kl, *hh, *hl, *wh, *wl;
    unsigned* syncp;
    cudaGetSymbolAddress((void**)&keys, g_keys);
    cudaGetSymbolAddress((void**)&wk,   g_wk);
    cudaGetSymbolAddress((void**)&Gx,   g_Gx);
    cudaGetSymbolAddress((void**)&syncp, g_sync);
    cudaGetSymbolAddress((void**)&xh, g_x_hi);   cudaGetSymbolAddress((void**)&xl, g_x_lo);
    cudaGetSymbolAddress((void**)&ph, g_p_hi);   cudaGetSymbolAddress((void**)&pl, g_p_lo);
    cudaGetSymbolAddress((void**)&kvh, g_kvw_hi); cudaGetSymbolAddress((void**)&kvl, g_kvw_lo);
    cudaGetSymbolAddress((void**)&awh, g_awk_hi); cudaGetSymbolAddress((void**)&awl, g_awk_lo);
    cudaGetSymbolAddress((void**)&wihx_h, g_wih_hi); cudaGetSymbolAddress((void**)&wihx_l, g_wih_lo);
    cudaGetSymbolAddress((void**)&kh, g_keys_hi); cudaGetSymbolAddress((void**)&kl, g_keys_lo);
    cudaGetSymbolAddress((void**)&hh, g_hall_hi); cudaGetSymbolAddress((void**)&hl, g_hall_lo);
    cudaGetSymbolAddress((void**)&wh, g_w_hi);    cudaGetSymbolAddress((void**)&wl, g_w_lo);

    cudaMemsetAsync(syncp, 0, FS_TOTAL * sizeof(unsigned));

    cudaFuncSetAttribute(decode_loop, cudaFuncAttributeMaxDynamicSharedMemorySize, DEC_SMEM);
    cudaFuncSetAttribute(mma_nt, cudaFuncAttributeMaxDynamicSharedMemorySize, MMA_SMEM);

    gather_conv<<<NB_GATH + NB_OUTW + NB_PTCH + NB_KVW + NB_AWK + NB_WIHX + NB_WHH + NB_WH + NB_WIHC, 256>>>(
        tgt, emb, outW, patches, kvW, aWk, Wih, Whh, aWh);

    // keys = patches @ kvW^T + kvb     [6272 x 512], K=768 (also emit bf16 split)
    mma_nt<<<dim3(4, 49), 256, MMA_SMEM>>>(ph, pl, kvh, kvl, kvb, nullptr,
                                           keys, 512, 512, 24, 768, 768, kh, kl);
    // wk = keys @ aWk^T                [6272 x 512], K=512
    mma_nt<<<dim3(4, 49), 256, MMA_SMEM>>>(kh, kl, awh, awl, nullptr, nullptr,
                                           wk, 512, 512, 16, 512, 512, nullptr, nullptr);
    // Gx = x @ Wih_x^T + b_ih + b_hh   [4096 x 2048], K=512
    mma_nt<<<dim3(16, 32), 256, MMA_SMEM>>>(xh, xl, wihx_h, wihx_l, bih, bhh,
                                            Gx, 2048, 2048, 16, 512, 512, nullptr, nullptr);

    decode_loop<<<GRID_P, 256, DEC_SMEM>>>(av, lnw, lnb, cls, ihW, ihb, icW, icb);

    // logits = hall @ outW^T + outb    [4096 x 10000], K=512
    mma_nt<<<dim3(79, 32), 256, MMA_SMEM>>>(hh, hl, wh, wl, outb, nullptr,
                                            out, VV, VV, 16, 512, 512, nullptr, nullptr);
}

// round 17
// speedup vs baseline: 1.0243x; 1.0243x over previous
#include <cuda_runtime.h>
#include <cuda_bf16.h>
#include <math.h>
#include <stdint.h>

#define BB 32
#define NN 196
#define TT 128
#define DH 512
#define VV 10000
#define VPAD 10112
#define GRID_P 128

typedef __nv_bfloat16 bf16;

// decode smem: 4 banks (Whwh, Wgx, Wgh, A) x hi/lo, each [32 rows][264 bf16]
#define KST2 264
#define ABANK (32 * KST2)
#define OFF_WHH_HI 0
#define OFF_WHH_LO (1 * ABANK)
#define OFF_WGX_HI (2 * ABANK)
#define OFF_WGX_LO (3 * ABANK)
#define OFF_WGH_HI (4 * ABANK)
#define OFF_WGH_LO (5 * ABANK)
#define OFF_A_HI   (6 * ABANK)
#define OFF_A_LO   (7 * ABANK)
#define DEC_SMEM (8 * ABANK * 2)       // 135,168 bytes

// flag layout (words; 64-word line stride)
#define FS_INIT 0
#define FS_HWH  64
#define FS_CTX  128
#define FS_GX   192
#define FS_GH   256
#define FS_H    320
#define FS_MINI 1024                   // + b*64
#define FS_TOTAL (1024 + BB * 64)

// ---------------- device scratch (static, no allocation) ----------------
__device__ float g_keys[BB * NN * DH];
__device__ float g_wk  [BB * NN * DH];
__device__ float g_Gx  [BB * TT * 4 * DH];
__device__ float g_c   [BB * DH];
__device__ float g_hwhp[8][BB * DH];         // hwh k-partials
__device__ float g_gxp [2][BB * 4 * DH];     // ctx-gate k-partials
__device__ float g_ghp [2][BB * 4 * DH];     // h-gate k-partials
__device__ float g_ctxp[4][BB * DH];
__device__ float g_cm[BB * 4], g_cs[BB * 4];
__device__ unsigned g_sync[FS_TOTAL];
__device__ bf16 g_hall_hi[BB * TT * DH], g_hall_lo[BB * TT * DH];
__device__ bf16 g_w_hi[VPAD * DH], g_w_lo[VPAD * DH];   // rows >= VV stay zero
__device__ bf16 g_x_hi[BB * TT * DH], g_x_lo[BB * TT * DH];
__device__ bf16 g_p_hi[BB * NN * 768], g_p_lo[BB * NN * 768];
__device__ bf16 g_kvw_hi[512 * 768], g_kvw_lo[512 * 768];
__device__ bf16 g_awk_hi[512 * 512], g_awk_lo[512 * 512];
__device__ bf16 g_wih_hi[2048 * 512], g_wih_lo[2048 * 512];     // Wih x-half
__device__ bf16 g_keys_hi[BB * NN * DH], g_keys_lo[BB * NN * DH];
__device__ bf16 g_whh_hi[2048 * 512], g_whh_lo[2048 * 512];     // W_hh
__device__ bf16 g_wh_hi[512 * 512],  g_wh_lo[512 * 512];        // attn_Wh
__device__ bf16 g_wihc_hi[2048 * 512], g_wihc_lo[2048 * 512];   // Wih ctx-half
__device__ bf16 g_hb_hi[BB * DH], g_hb_lo[BB * DH];             // current h
__device__ bf16 g_ctxb_hi[BB * DH], g_ctxb_lo[BB * DH];         // current ctx

__device__ __forceinline__ float fast_tanh(float x) {
    float y; asm("tanh.approx.f32 %0, %1;" : "=f"(y) : "f"(x)); return y;
}
__device__ __forceinline__ float sigm(float x) { return 1.f / (1.f + expf(-x)); }
__device__ __forceinline__ void split_bf16(float v, bf16* hi, bf16* lo) {
    const bf16 h = __float2bfloat16(v);
    *hi = h;
    *lo = __float2bfloat16(v - __bfloat162float(h));
}

// release-arrive / acquire-poll primitives
__device__ __forceinline__ void red_release_add(unsigned* p) {
    asm volatile("red.release.gpu.global.add.u32 [%0], %1;" :: "l"(p), "r"(1u) : "memory");
}
__device__ __forceinline__ unsigned ld_acquire(const unsigned* p) {
    unsigned v;
    asm volatile("ld.acquire.gpu.global.u32 %0, [%1];" : "=r"(v) : "l"(p) : "memory");
    return v;
}
__device__ __forceinline__ void wait_flag(unsigned* p, unsigned target) {
    while (ld_acquire(p) < target) { __nanosleep(20); }
}

// ---------------- mma.sync helpers ----------------
__device__ __forceinline__ uint32_t smem_u32(const void* p) {
    uint32_t a;
    asm("{ .reg .u64 t; cvta.to.shared.u64 t, %1; cvt.u32.u64 %0, t; }" : "=r"(a) : "l"(p));
    return a;
}
__device__ __forceinline__ void ldsm4(uint32_t* r, uint32_t addr) {
    asm volatile("ldmatrix.sync.aligned.m8n8.x4.shared.b16 {%0,%1,%2,%3}, [%4];"
        : "=r"(r[0]), "=r"(r[1]), "=r"(r[2]), "=r"(r[3]) : "r"(addr));
}
__device__ __forceinline__ void ldsm2(uint32_t* r, uint32_t addr) {
    asm volatile("ldmatrix.sync.aligned.m8n8.x2.shared.b16 {%0,%1}, [%2];"
        : "=r"(r[0]), "=r"(r[1]) : "r"(addr));
}
__device__ __forceinline__ void mma16816(float* c, const uint32_t* a, const uint32_t* b) {
    asm volatile("mma.sync.aligned.m16n8k16.row.col.f32.bf16.bf16.f32 "
        "{%0,%1,%2,%3}, {%4,%5,%6,%7}, {%8,%9}, {%0,%1,%2,%3};"
        : "+f"(c[0]), "+f"(c[1]), "+f"(c[2]), "+f"(c[3])
        : "r"(a[0]), "r"(a[1]), "r"(a[2]), "r"(a[3]), "r"(b[0]), "r"(b[1]));
}
__device__ __forceinline__ void cp16(uint32_t smem_addr, const void* gptr) {
    asm volatile("cp.async.cg.shared.global [%0], [%1], 16;"
        :: "r"(smem_addr), "l"(gptr));
}
#define CP_COMMIT() asm volatile("cp.async.commit_group;" ::: "memory")
#define CP_WAIT(n)  asm volatile("cp.async.wait_group %0;" :: "n"(n) : "memory")

// ---------------- generic split-bf16 MMA GEMM (validated) ----------------
#define LSTR 40
#define MAT_B (128 * LSTR * 2)
#define BUF_B (4 * MAT_B)
#define MMA_SMEM (2 * BUF_B)
__global__ __launch_bounds__(256, 2) void mma_nt(
    const bf16* __restrict__ Ah, const bf16* __restrict__ Al,
    const bf16* __restrict__ Bh, const bf16* __restrict__ Bl,
    const float* __restrict__ bias1, const float* __restrict__ bias2,
    float* __restrict__ C, int ldc, int nLimit, int kChunks, int ldA, int ldB,
    bf16* __restrict__ Chi, bf16* __restrict__ Clo)
{
    extern __shared__ char lsm[];
    const uint32_t u0 = smem_u32(lsm);

    const int tid = threadIdx.x;
    const int wid = tid >> 5, lane = tid & 31;
    const int nBase = blockIdx.x * 128;
    const int mBase = blockIdx.y * 128;
    const int wm = (wid & 3) * 32;
    const int wn = (wid >> 2) * 64;

    float acc[2][8][4];
#pragma unroll
    for (int i = 0; i < 2; i++)
#pragma unroll
        for (int j = 0; j < 8; j++)
#pragma unroll
            for (int k = 0; k < 4; k++) acc[i][j][k] = 0.f;

    const int cr = tid >> 1;
    const int cs = (tid & 1) * 2;

    const bf16* gsrc[4] = {
        Ah + (size_t)(mBase + cr) * ldA, Al + (size_t)(mBase + cr) * ldA,
        Bh + (size_t)(nBase + cr) * ldB, Bl + (size_t)(nBase + cr) * ldB };
    const uint32_t sdst = u0 + (cr * LSTR + cs * 8) * 2;

    auto stage = [&](int ch, int buf) {
        const int goff = ch * 32 + cs * 8;
#pragma unroll
        for (int m = 0; m < 4; m++) {
            const uint32_t d = sdst + buf * BUF_B + m * MAT_B;
            cp16(d, gsrc[m] + goff);
            cp16(d + 16, gsrc[m] + goff + 8);
        }
        CP_COMMIT();
    };

    stage(0, 0);

    for (int ch = 0; ch < kChunks; ch++) {
        const int cur = ch & 1;
        if (ch + 1 < kChunks) { stage(ch + 1, cur ^ 1); CP_WAIT(1); }
        else                  { CP_WAIT(0); }
        __syncthreads();

        const uint32_t uAh = u0 + cur * BUF_B;
        const uint32_t uAl = uAh + MAT_B;
        const uint32_t uBh = uAl + MAT_B;
        const uint32_t uBl = uBh + MAT_B;

#pragma unroll
        for (int ks = 0; ks < 2; ks++) {
            uint32_t ah[2][4], al[2][4], bh[8][2], bl[8][2];
#pragma unroll
            for (int mt = 0; mt < 2; mt++) {
                const uint32_t off =
                    ((wm + mt * 16 + (lane & 15)) * LSTR + ks * 16 + (lane >> 4) * 8) * 2;
                ldsm4(ah[mt], uAh + off);
                ldsm4(al[mt], uAl + off);
            }
#pragma unroll
            for (int p = 0; p < 4; p++) {
                const uint32_t off =
                    ((wn + p * 16 + ((lane >> 4) & 1) * 8 + (lane & 7)) * LSTR +
                     ks * 16 + ((lane >> 3) & 1) * 8) * 2;
                uint32_t r4[4];
                ldsm4(r4, uBh + off);
                bh[2 * p][0] = r4[0]; bh[2 * p][1] = r4[1];
                bh[2 * p + 1][0] = r4[2]; bh[2 * p + 1][1] = r4[3];
                ldsm4(r4, uBl + off);
                bl[2 * p][0] = r4[0]; bl[2 * p][1] = r4[1];
                bl[2 * p + 1][0] = r4[2]; bl[2 * p + 1][1] = r4[3];
            }
#pragma unroll
            for (int mt = 0; mt < 2; mt++)
#pragma unroll
                for (int nt = 0; nt < 8; nt++) {
                    mma16816(acc[mt][nt], ah[mt], bh[nt]);
                    mma16816(acc[mt][nt], ah[mt], bl[nt]);
                    mma16816(acc[mt][nt], al[mt], bh[nt]);
                }
        }
        __syncthreads();
    }

    const int erow = lane >> 2;
    const int ecol = (lane & 3) * 2;
#pragma unroll
    for (int mt = 0; mt < 2; mt++) {
#pragma unroll
        for (int nt = 0; nt < 8; nt++) {
            const int gn = nBase + wn + nt * 8 + ecol;
            if (gn >= nLimit) continue;
            float b0 = 0.f, b1 = 0.f;
            if (bias1) { b0 += bias1[gn]; b1 += bias1[gn + 1]; }
            if (bias2) { b0 += bias2[gn]; b1 += bias2[gn + 1]; }
            const int r0 = mBase + wm + mt * 16 + erow;
            const float v00 = acc[mt][nt][0] + b0, v01 = acc[mt][nt][1] + b1;
            const float v10 = acc[mt][nt][2] + b0, v11 = acc[mt][nt][3] + b1;
            if (C) {
                *(float2*)&C[(size_t)r0 * ldc + gn] = make_float2(v00, v01);
                *(float2*)&C[(size_t)(r0 + 8) * ldc + gn] = make_float2(v10, v11);
            }
            if (Chi) {
                const size_t i0 = (size_t)r0 * ldc + gn;
                const size_t i1 = (size_t)(r0 + 8) * ldc + gn;
                split_bf16(v00, &Chi[i0], &Clo[i0]);
                split_bf16(v01, &Chi[i0 + 1], &Clo[i0 + 1]);
                split_bf16(v10, &Chi[i1], &Clo[i1]);
                split_bf16(v11, &Chi[i1 + 1], &Clo[i1 + 1]);
            }
        }
    }
}

// ---------------- all input conversions + embedding gather ----------------
#define NB_GATH 8192
#define NB_OUTW 20000
#define NB_PTCH 18816
#define NB_KVW  1536
#define NB_AWK  1024
#define NB_WIHX 4096
#define NB_WHH  4096
#define NB_WH   1024
#define NB_WIHC 4096
__global__ void gather_conv(const int* __restrict__ ids, const float* __restrict__ emb,
                            const float* __restrict__ outW, const float* __restrict__ patches,
                            const float* __restrict__ kvW, const float* __restrict__ aWk,
                            const float* __restrict__ Wih, const float* __restrict__ Whh,
                            const float* __restrict__ aWh)
{
    int blk = blockIdx.x;
    const int tid = threadIdx.x;
    if (blk < NB_GATH) {
        const int i = blk * 256 + tid;
        const int d = i & (DH - 1);
        const int bt = i >> 9;
        split_bf16(emb[(size_t)ids[bt] * DH + d], &g_x_hi[i], &g_x_lo[i]);
        return;
    }
    blk -= NB_GATH;
    if (blk < NB_OUTW) {
        const int j = blk * 256 + tid;
        if (j < VV * DH) split_bf16(outW[j], &g_w_hi[j], &g_w_lo[j]);
        return;
    }
    blk -= NB_OUTW;
    if (blk < NB_PTCH) {
        const int j = blk * 256 + tid;
        split_bf16(patches[j], &g_p_hi[j], &g_p_lo[j]);
        return;
    }
    blk -= NB_PTCH;
    if (blk < NB_KVW) {
        const int j = blk * 256 + tid;
        split_bf16(kvW[j], &g_kvw_hi[j], &g_kvw_lo[j]);
        return;
    }
    blk -= NB_KVW;
    if (blk < NB_AWK) {
        const int j = blk * 256 + tid;
        split_bf16(aWk[j], &g_awk_hi[j], &g_awk_lo[j]);
        return;
    }
    blk -= NB_AWK;
    if (blk < NB_WIHX) {
        const int j = blk * 256 + tid;
        const int r = j >> 9, c = j & 511;
        split_bf16(Wih[(size_t)r * 1024 + c], &g_wih_hi[j], &g_wih_lo[j]);
        return;
    }
    blk -= NB_WIHX;
    if (blk < NB_WHH) {
        const int j = blk * 256 + tid;
        split_bf16(Whh[j], &g_whh_hi[j], &g_whh_lo[j]);
        return;
    }
    blk -= NB_WHH;
    if (blk < NB_WH) {
        const int j = blk * 256 + tid;
        split_bf16(aWh[j], &g_wh_hi[j], &g_wh_lo[j]);
        return;
    }
    blk -= NB_WH;
    {
        const int j = blk * 256 + tid;
        const int r = j >> 9, c = j & 511;
        split_bf16(Wih[(size_t)r * 1024 + 512 + c], &g_wihc_hi[j], &g_wihc_lo[j]);
    }
}

// ---------------- persistent decode loop: k-split phases, all 128 CTAs busy ----------------
__global__ __launch_bounds__(256, 1) void decode_loop(
    const float* __restrict__ av,
    const float* __restrict__ lnw, const float* __restrict__ lnb,
    const float* __restrict__ cls,
    const float* __restrict__ ihW, const float* __restrict__ ihb,
    const float* __restrict__ icW, const float* __restrict__ icb)
{
    extern __shared__ bf16 dsm[];
    __shared__ float s_v[512];
    __shared__ float s_hwh[512];
    __shared__ float s_sc[49];
    __shared__ float s_e[64];
    __shared__ float s_r0[8], s_r1[8], s_mv[2];

    const int tid = threadIdx.x;
    const int bid = blockIdx.x;
    const int warp = tid >> 5, lane = tid & 31;
    const int gwarp = bid * 8 + warp;
    const uint32_t u0 = smem_u32(dsm);

    // job coordinates
    const int jn16 = bid & 15, jk16 = bid >> 4;   // hwh: 16 n-tiles x 8 k-slices(64)
    const int jn64 = bid & 63, jk64 = bid >> 6;   // gates: 64 n-tiles x 2 k-slices(256)

    // warp frag coords (shared across mma phases)
    const int mt = warp & 1, nt = warp >> 1;      // 2 m-tiles x 4 n-tiles(8)
    const int b0 = mt * 16 + (lane >> 2);
    const int ecol = (lane & 3) * 2;

    // ---- one-time weight staging ----
    // hwh weights: attn_Wh rows [jn16*32,+32), cols [jk16*64,+64)
    for (int idx = tid; idx < 32 * 8; idx += 256) {
        const int row = idx >> 3, seg = idx & 7;
        const size_t src = (size_t)(jn16 * 32 + row) * 512 + jk16 * 64 + seg * 8;
        *(uint4*)(dsm + OFF_WHH_HI + row * KST2 + seg * 8) = *(const uint4*)(g_wh_hi + src);
        *(uint4*)(dsm + OFF_WHH_LO + row * KST2 + seg * 8) = *(const uint4*)(g_wh_lo + src);
    }
    // gate weights: rows [jn64*32,+32), cols [jk64*256,+256)
    for (int idx = tid; idx < 32 * 32; idx += 256) {
        const int row = idx >> 5, seg = idx & 31;
        const size_t src = (size_t)(jn64 * 32 + row) * 512 + jk64 * 256 + seg * 8;
        *(uint4*)(dsm + OFF_WGX_HI + row * KST2 + seg * 8) = *(const uint4*)(g_wihc_hi + src);
        *(uint4*)(dsm + OFF_WGX_LO + row * KST2 + seg * 8) = *(const uint4*)(g_wihc_lo + src);
        *(uint4*)(dsm + OFF_WGH_HI + row * KST2 + seg * 8) = *(const uint4*)(g_whh_hi + src);
        *(uint4*)(dsm + OFF_WGH_LO + row * KST2 + seg * 8) = *(const uint4*)(g_whh_lo + src);
    }
    for (int k = tid; k < 512; k += 256) s_v[k] = av[k];

    // A-slice loader: 32 rows x (nsegs*8) cols from koff
    auto load_A = [&](const bf16* hi, const bf16* lo, int koff, int nsegs) {
        for (int idx = tid; idx < 32 * nsegs; idx += 256) {
            const int row = idx / nsegs, seg = idx - row * nsegs;
            const size_t src = (size_t)row * 512 + koff + seg * 8;
            *(uint4*)(dsm + OFF_A_HI + row * KST2 + seg * 8) = *(const uint4*)(hi + src);
            *(uint4*)(dsm + OFF_A_LO + row * KST2 + seg * 8) = *(const uint4*)(lo + src);
        }
    };

    auto gate_mma = [&](uint32_t uBh, uint32_t uBl, int nks, float* acc) {
        const uint32_t uAh = u0 + OFF_A_HI * 2, uAl = u0 + OFF_A_LO * 2;
        const uint32_t a_off = ((mt * 16 + (lane & 15)) * KST2 + (lane >> 4) * 8) * 2;
        const uint32_t b_off = ((nt * 8 + (lane & 7)) * KST2 + ((lane >> 3) & 1) * 8) * 2;
        for (int ks = 0; ks < nks; ks++) {
            const uint32_t kb = ks * 32;
            uint32_t ah[4], al[4], bh[2], bl[2];
            ldsm4(ah, uAh + a_off + kb);
            ldsm4(al, uAl + a_off + kb);
            ldsm2(bh, uBh + b_off + kb);
            ldsm2(bl, uBl + b_off + kb);
            mma16816(acc, ah, bh);
            mma16816(acc, ah, bl);
            mma16816(acc, al, bh);
        }
    };

    // ---- h0/c0 (folded) ----
    for (int j = gwarp; j < 2 * BB * DH; j += GRID_P * 8) {
        const int sel = (j >= BB * DH);
        const int r = sel ? j - BB * DH : j;
        const int b = r >> 9, d = r & (DH - 1);
        const float4* W4 = (const float4*)((sel ? icW : ihW) + (size_t)d * 768);
        const float4* x4 = (const float4*)(cls + (size_t)b * 768);
        float acc = 0.f;
#pragma unroll
        for (int p = 0; p < 6; p++) {
            float4 w = W4[lane + 32 * p];
            float4 x = x4[lane + 32 * p];
            acc += w.x * x.x + w.y * x.y + w.z * x.z + w.w * x.w;
        }
#pragma unroll
        for (int o = 16; o; o >>= 1) acc += __shfl_xor_sync(0xffffffffu, acc, o);
        if (lane == 0) {
            if (sel) g_c[b * DH + d] = acc + icb[d];
            else     split_bf16(acc + ihb[d], &g_hb_hi[b * DH + d], &g_hb_lo[b * DH + d]);
        }
    }
    __syncthreads();
    if (tid == 0) {
        red_release_add(&g_sync[FS_INIT]);
        wait_flag(&g_sync[FS_INIT], (unsigned)GRID_P);
    }
    __syncthreads();

    for (int t = 0; t < TT; t++) {
        // ======== hwh phase: all 128 CTAs, k-split 8 ========
        if (tid == 0 && t > 0) wait_flag(&g_sync[FS_H], 32u * (unsigned)t);
        __syncthreads();
        load_A(g_hb_hi, g_hb_lo, jk16 * 64, 8);
        __syncthreads();
        {
            float acc[4] = {0.f, 0.f, 0.f, 0.f};
            gate_mma(u0 + OFF_WHH_HI * 2, u0 + OFF_WHH_LO * 2, 4, acc);
            const int r = jn16 * 32 + nt * 8 + ecol;
            g_hwhp[jk16][b0 * 512 + r] = acc[0];       g_hwhp[jk16][b0 * 512 + r + 1] = acc[1];
            g_hwhp[jk16][(b0 + 8) * 512 + r] = acc[2]; g_hwhp[jk16][(b0 + 8) * 512 + r + 1] = acc[3];
        }
        __syncthreads();
        if (tid == 0) red_release_add(&g_sync[FS_HWH]);

        // ======== B phase: all 128 CTAs ========
        if (tid == 0) wait_flag(&g_sync[FS_HWH], 128u * (unsigned)(t + 1));
        __syncthreads();
        {
            const int b = bid >> 2, p = bid & 3;
            for (int k = tid; k < 512; k += 256) {
                float s = 0.f;
#pragma unroll
                for (int q = 0; q < 8; q++) s += g_hwhp[q][b * 512 + k];
                s_hwh[k] = s;
            }
            __syncthreads();

            for (int n = warp; n < 49; n += 8) {
                const int ng = p * 49 + n;
                const float4* wk4 = (const float4*)(g_wk + ((size_t)(b * NN + ng)) * 512);
                const float4* hw4 = (const float4*)s_hwh;
                const float4* v4  = (const float4*)s_v;
                float s = 0.f;
#pragma unroll
                for (int i = 0; i < 4; i++) {
                    const float4 a = wk4[lane + 32 * i];
                    const float4 c = hw4[lane + 32 * i];
                    const float4 w = v4[lane + 32 * i];
                    s += fast_tanh(a.x + c.x) * w.x + fast_tanh(a.y + c.y) * w.y +
                         fast_tanh(a.z + c.z) * w.z + fast_tanh(a.w + c.w) * w.w;
                }
#pragma unroll
                for (int o = 16; o; o >>= 1) s += __shfl_xor_sync(0xffffffffu, s, o);
                if (lane == 0) s_sc[n] = s;
            }
            __syncthreads();

            if (warp == 0) {
                const float x0 = (lane < 49) ? s_sc[lane] : -1e30f;
                const float x1 = (lane + 32 < 49) ? s_sc[lane + 32] : -1e30f;
                float m = fmaxf(x0, x1);
#pragma unroll
                for (int o = 16; o; o >>= 1) m = fmaxf(m, __shfl_xor_sync(0xffffffffu, m, o));
                const float e0 = (lane < 49) ? __expf(x0 - m) : 0.f;
                const float e1 = (lane + 32 < 49) ? __expf(x1 - m) : 0.f;
                if (lane < 49) s_e[lane] = e0;
                if (lane + 32 < 49) s_e[lane + 32] = e1;
                float su = e0 + e1;
#pragma unroll
                for (int o = 16; o; o >>= 1) su += __shfl_xor_sync(0xffffffffu, su, o);
                if (lane == 0) { g_cm[b * 4 + p] = m; g_cs[b * 4 + p] = su; }
            }
            __syncthreads();

#pragma unroll
            for (int u = 0; u < 2; u++) {
                const int d = tid + 256 * u;
                const float* Kp = g_keys + ((size_t)(b * NN + p * 49)) * 512 + d;
                float a = 0.f;
#pragma unroll 7
                for (int i = 0; i < 49; i++) a = fmaf(s_e[i], Kp[(size_t)i * 512], a);
                g_ctxp[p][b * 512 + d] = a;
            }

            __syncthreads();
            if (tid == 0) {
                red_release_add(&g_sync[FS_MINI + b * 64]);
                wait_flag(&g_sync[FS_MINI + b * 64], 4u * (unsigned)(t + 1));
            }
            __syncthreads();

            if (tid < 128) {
                const int d = p * 128 + tid;
                const float m0 = g_cm[b*4+0], m1 = g_cm[b*4+1], m2 = g_cm[b*4+2], m3 = g_cm[b*4+3];
                const float m = fmaxf(fmaxf(m0, m1), fmaxf(m2, m3));
                const float e0 = __expf(m0 - m), e1 = __expf(m1 - m);
                const float e2 = __expf(m2 - m), e3 = __expf(m3 - m);
                const float den = e0 * g_cs[b*4+0] + e1 * g_cs[b*4+1] +
                                  e2 * g_cs[b*4+2] + e3 * g_cs[b*4+3];
                const float v = (e0 * g_ctxp[0][b*512+d] + e1 * g_ctxp[1][b*512+d] +
                                 e2 * g_ctxp[2][b*512+d] + e3 * g_ctxp[3][b*512+d]) / den;
                split_bf16(v, &g_ctxb_hi[b * 512 + d], &g_ctxb_lo[b * 512 + d]);
            }
        }
        __syncthreads();
        if (tid == 0) red_release_add(&g_sync[FS_CTX]);

        // ======== gh job (no wait: h stable until D) ========
        load_A(g_hb_hi, g_hb_lo, jk64 * 256, 32);
        __syncthreads();
        {
            float acc[4] = {0.f, 0.f, 0.f, 0.f};
            gate_mma(u0 + OFF_WGH_HI * 2, u0 + OFF_WGH_LO * 2, 16, acc);
            const int r = jn64 * 32 + nt * 8 + ecol;
            g_ghp[jk64][b0 * 2048 + r] = acc[0];       g_ghp[jk64][b0 * 2048 + r + 1] = acc[1];
            g_ghp[jk64][(b0 + 8) * 2048 + r] = acc[2]; g_ghp[jk64][(b0 + 8) * 2048 + r + 1] = acc[3];
        }
        __syncthreads();
        if (tid == 0) red_release_add(&g_sync[FS_GH]);

        // ======== gx job (needs ctx) ========
        if (tid == 0) wait_flag(&g_sync[FS_CTX], 128u * (unsigned)(t + 1));
        __syncthreads();
        load_A(g_ctxb_hi, g_ctxb_lo, jk64 * 256, 32);
        __syncthreads();
        {
            float acc[4] = {0.f, 0.f, 0.f, 0.f};
            gate_mma(u0 + OFF_WGX_HI * 2, u0 + OFF_WGX_LO * 2, 16, acc);
            const int r = jn64 * 32 + nt * 8 + ecol;
            g_gxp[jk64][b0 * 2048 + r] = acc[0];       g_gxp[jk64][b0 * 2048 + r + 1] = acc[1];
            g_gxp[jk64][(b0 + 8) * 2048 + r] = acc[2]; g_gxp[jk64][(b0 + 8) * 2048 + r + 1] = acc[3];
        }
        __syncthreads();
        if (tid == 0) red_release_add(&g_sync[FS_GX]);

        // ======== D phase (32 CTAs): cell + LayerNorm ========
        if (bid < 32) {
            if (tid == 0) {
                wait_flag(&g_sync[FS_GX], 128u * (unsigned)(t + 1));
                wait_flag(&g_sync[FS_GH], 128u * (unsigned)(t + 1));
            }
            __syncthreads();
            const int b = bid;
            const float* Gx = g_Gx + ((size_t)(b * TT + t)) * 2048;
            float hr[2];
            float sum = 0.f, ssq = 0.f;
#pragma unroll
            for (int u = 0; u < 2; u++) {
                const int d = tid + 256 * u;
                const size_t gb = (size_t)b * 2048;
                const float gi = Gx[d] + g_gxp[0][gb + d] + g_gxp[1][gb + d]
                                       + g_ghp[0][gb + d] + g_ghp[1][gb + d];
                const float gf = Gx[512 + d] + g_gxp[0][gb + 512 + d] + g_gxp[1][gb + 512 + d]
                                             + g_ghp[0][gb + 512 + d] + g_ghp[1][gb + 512 + d];
                const float gg = Gx[1024 + d] + g_gxp[0][gb + 1024 + d] + g_gxp[1][gb + 1024 + d]
                                              + g_ghp[0][gb + 1024 + d] + g_ghp[1][gb + 1024 + d];
                const float go = Gx[1536 + d] + g_gxp[0][gb + 1536 + d] + g_gxp[1][gb + 1536 + d]
                                              + g_ghp[0][gb + 1536 + d] + g_ghp[1][gb + 1536 + d];
                const float c_old = g_c[b * DH + d];
                const float cn = sigm(gf) * c_old + sigm(gi) * tanhf(gg);
                g_c[b * DH + d] = cn;
                const float h = sigm(go) * tanhf(cn);
                hr[u] = h; sum += h; ssq += h * h;
            }
#pragma unroll
            for (int o = 16; o; o >>= 1) {
                sum += __shfl_xor_sync(0xffffffffu, sum, o);
                ssq += __shfl_xor_sync(0xffffffffu, ssq, o);
            }
            if (lane == 0) { s_r0[warp] = sum; s_r1[warp] = ssq; }
            __syncthreads();
            if (tid < 8) {
                float s = s_r0[tid], qq = s_r1[tid];
#pragma unroll
                for (int o = 4; o; o >>= 1) {
                    s += __shfl_xor_sync(0x000000ffu, s, o);
                    qq += __shfl_xor_sync(0x000000ffu, qq, o);
                }
                if (tid == 0) { s_mv[0] = s * (1.f / DH); s_mv[1] = qq * (1.f / DH); }
            }
            __syncthreads();
            const float mu = s_mv[0];
            const float var = s_mv[1] - mu * mu;
            const float rstd = rsqrtf(var + 1e-5f);
#pragma unroll
            for (int u = 0; u < 2; u++) {
                const int d = tid + 256 * u;
                const float h = (hr[u] - mu) * rstd * lnw[d] + lnb[d];
                const bf16 hi = __float2bfloat16(h);
                const bf16 lo = __float2bfloat16(h - __bfloat162float(hi));
                const size_t idx = ((size_t)(b * TT + t)) * DH + d;
                g_hall_hi[idx] = hi; g_hall_lo[idx] = lo;
                g_hb_hi[b * DH + d] = hi; g_hb_lo[b * DH + d] = lo;
            }
            __syncthreads();
            if (tid == 0) red_release_add(&g_sync[FS_H]);
        }
    }
}

// ---------------- launch ----------------
extern "C" void kernel_launch(void* const* d_in, const int* in_sizes, int n_in,
                              void* d_out, int out_size)
{
    const float* patches = (const float*)d_in[0];
    const float* cls     = (const float*)d_in[1];
    const int*   tgt     = (const int*)  d_in[2];
    const float* emb     = (const float*)d_in[3];
    const float* kvW     = (const float*)d_in[4];
    const float* kvb     = (const float*)d_in[5];
    const float* ihW     = (const float*)d_in[6];
    const float* ihb     = (const float*)d_in[7];
    const float* icW     = (const float*)d_in[8];
    const float* icb     = (const float*)d_in[9];
    const float* aWh     = (const float*)d_in[10];
    const float* aWk     = (const float*)d_in[11];
    const float* av      = (const float*)d_in[12];
    const float* Wih     = (const float*)d_in[13];
    const float* Whh     = (const float*)d_in[14];
    const float* bih     = (const float*)d_in[15];
    const float* bhh     = (const float*)d_in[16];
    const float* lnw     = (const float*)d_in[17];
    const float* lnb     = (const float*)d_in[18];
    const float* outW    = (const float*)d_in[19];
    const float* outb    = (const float*)d_in[20];
    float* out = (float*)d_out;

    float *keys, *wk, *Gx;
    bf16 *xh, *xl, *ph, *pl, *kvh, *kvl, *awh, *awl, *wihx_h, *wihx_l;
    bf16 *kh, *kl, *hh, *hl, *wh, *wl;
    unsigned* syncp;
    cudaGetSymbolAddress((void**)&keys, g_keys);
    cudaGetSymbolAddress((void**)&wk,   g_wk);
    cudaGetSymbolAddress((void**)&Gx,   g_Gx);
    cudaGetSymbolAddress((void**)&syncp, g_sync);
    cudaGetSymbolAddress((void**)&xh, g_x_hi);   cudaGetSymbolAddress((void**)&xl, g_x_lo);
    cudaGetSymbolAddress((void**)&ph, g_p_hi);   cudaGetSymbolAddress((void**)&pl, g_p_lo);
    cudaGetSymbolAddress((void**)&kvh, g_kvw_hi); cudaGetSymbolAddress((void**)&kvl, g_kvw_lo);
    cudaGetSymbolAddress((void**)&awh, g_awk_hi); cudaGetSymbolAddress((void**)&awl, g_awk_lo);
    cudaGetSymbolAddress((void**)&wihx_h, g_wih_hi); cudaGetSymbolAddress((void**)&wihx_l, g_wih_lo);
    cudaGetSymbolAddress((void**)&kh, g_keys_hi); cudaGetSymbolAddress((void**)&kl, g_keys_lo);
    cudaGetSymbolAddress((void**)&hh, g_hall_hi); cudaGetSymbolAddress((void**)&hl, g_hall_lo);
    cudaGetSymbolAddress((void**)&wh, g_w_hi);    cudaGetSymbolAddress((void**)&wl, g_w_lo);

    cudaMemsetAsync(syncp, 0, FS_TOTAL * sizeof(unsigned));

    cudaFuncSetAttribute(decode_loop, cudaFuncAttributeMaxDynamicSharedMemorySize, DEC_SMEM);
    cudaFuncSetAttribute(mma_nt, cudaFuncAttributeMaxDynamicSharedMemorySize, MMA_SMEM);

    gather_conv<<<NB_GATH + NB_OUTW + NB_PTCH + NB_KVW + NB_AWK + NB_WIHX + NB_WHH + NB_WH + NB_WIHC, 256>>>(
        tgt, emb, outW, patches, kvW, aWk, Wih, Whh, aWh);

    // keys = patches @ kvW^T + kvb     [6272 x 512], K=768 (also emit bf16 split)
    mma_nt<<<dim3(4, 49), 256, MMA_SMEM>>>(ph, pl, kvh, kvl, kvb, nullptr,
                                           keys, 512, 512, 24, 768, 768, kh, kl);
    // wk = keys @ aWk^T                [6272 x 512], K=512
    mma_nt<<<dim3(4, 49), 256, MMA_SMEM>>>(kh, kl, awh, awl, nullptr, nullptr,
                                           wk, 512, 512, 16, 512, 512, nullptr, nullptr);
    // Gx = x @ Wih_x^T + b_ih + b_hh   [4096 x 2048], K=512
    mma_nt<<<dim3(16, 32), 256, MMA_SMEM>>>(xh, xl, wihx_h, wihx_l, bih, bhh,
                                            Gx, 2048, 2048, 16, 512, 512, nullptr, nullptr);

    decode_loop<<<GRID_P, 256, DEC_SMEM>>>(av, lnw, lnb, cls, ihW, ihb, icW, icb);

    // logits = hall @ outW^T + outb    [4096 x 10000], K=512
    mma_nt<<<dim3(79, 32), 256, MMA_SMEM>>>(hh, hl, wh, wl, outb, nullptr,
                                            out, VV, VV, 16, 512, 512, nullptr, nullptr);
}